// round 6
// baseline (speedup 1.0000x reference)
#include <cuda_runtime.h>
#include <cuda_bf16.h>

#define B 8
#define S 512
#define E 64
#define H 8
#define BH (B*H)
#define NBLK 256
#define NTHR 512

__device__ float g_ctx[B * S * E];
__device__ unsigned int g_bar_count;            // zero-init; self-resetting
__device__ volatile unsigned int g_bar_phase;   // monotonically increasing

// ---- packed f32x2 helpers (sm_103a) ---------------------------------------
__device__ __forceinline__ unsigned long long pk2(float lo, float hi) {
    unsigned long long r;
    asm("mov.b64 %0, {%1, %2};" : "=l"(r) : "f"(lo), "f"(hi));
    return r;
}
__device__ __forceinline__ void upk2(unsigned long long v, float& lo, float& hi) {
    asm("mov.b64 {%0, %1}, %2;" : "=f"(lo), "=f"(hi) : "l"(v));
}
__device__ __forceinline__ unsigned long long fma2(unsigned long long a,
                                                   unsigned long long b,
                                                   unsigned long long c) {
    unsigned long long d;
    asm("fma.rn.f32x2 %0, %1, %2, %3;" : "=l"(d) : "l"(a), "l"(b), "l"(c));
    return d;
}
__device__ __forceinline__ unsigned long long mul2(unsigned long long a,
                                                   unsigned long long b) {
    unsigned long long d;
    asm("mul.rn.f32x2 %0, %1, %2;" : "=l"(d) : "l"(a), "l"(b));
    return d;
}

// Shared memory reused across the two phases.
union __align__(16) SmemU {
    float Ks[S * 8];                 // phase 1: K tile, 16 KB
    struct {
        float Wt[64][68];            // phase 2: W transposed (Wt[k][e]), padded
        float bs[64];
    } p2;
};

// ---------------------------------------------------------------------------
// One persistent kernel: phase 1 = quantum heads + attention (R2 config),
// grid barrier, phase 2 = output projection on the already-resident blocks.
// 256 blocks x 512 threads, 2 blocks/SM guaranteed -> barrier is safe.
// ---------------------------------------------------------------------------
__global__ void __launch_bounds__(NTHR, 2) fused_kernel(
    const float* __restrict__ x,      // [B, S, E]
    const float* __restrict__ theta,  // [8]
    const float* __restrict__ W,      // [64, 64] (e, k)
    const float* __restrict__ bo,     // [64]
    float* __restrict__ out)          // [4096, 64]
{
    __shared__ SmemU sm;
    const int bid = blockIdx.x;       // 0..255
    const int tid = threadIdx.x;      // 0..511

    // ======================= Phase 1: qattn ================================
    {
        const int bh = bid & 63;
        const int b  = bh >> 3;
        const int h  = bh & 7;
        const int chunk = bid >> 6;   // 0..3

        float th[8];
#pragma unroll
        for (int j = 0; j < 8; ++j) th[j] = __ldg(theta + j);

        // Build K: one row per thread.
        {
            const float* xr = x + ((size_t)(b * S + tid)) * E + h * 8;
            float4 v0 = *(const float4*)(xr);
            float4 v1 = *(const float4*)(xr + 4);
            float c0 = __cosf(v0.x + th[0]);
            float c1 = __cosf(v0.y + th[1]);
            float c2 = __cosf(v0.z + th[2]);
            float c3 = __cosf(v0.w + th[3]);
            float c4 = __cosf(v1.x + th[4]);
            float c5 = __cosf(v1.y + th[5]);
            float c6 = __cosf(v1.z + th[6]);
            float c7 = __cosf(v1.w + th[7]);
            float q1 = c0 * c1;
            float q2 = q1 * c2;
            float q3 = q2 * c3;
            float q4 = q3 * c4;
            float q5 = q4 * c5;
            float q6 = q5 * c6;
            float q7 = q6 * c7;
            float q0 = c1 * c2 * c3 * c4 * c5 * c6 * c7;
            ((float4*)sm.Ks)[tid * 2 + 0] = make_float4(q0, q1, q2, q3);
            ((float4*)sm.Ks)[tid * 2 + 1] = make_float4(q4, q5, q6, q7);
        }
        __syncthreads();

        const int q = chunk * 128 + (tid >> 2);  // query row
        const int g = tid & 3;                   // key-split lane

        const float sc = 0.35355339059327373f * 1.4426950408889634f;
        float4 qa = ((const float4*)sm.Ks)[q * 2 + 0];
        float4 qb = ((const float4*)sm.Ks)[q * 2 + 1];
        unsigned long long q01 = pk2(qa.x * sc, qa.y * sc);
        unsigned long long q23 = pk2(qa.z * sc, qa.w * sc);
        unsigned long long q45 = pk2(qb.x * sc, qb.y * sc);
        unsigned long long q67 = pk2(qb.z * sc, qb.w * sc);

        unsigned long long acc01 = 0ull, acc23 = 0ull, acc45 = 0ull, acc67 = 0ull;
        float l = 0.f;

        const ulonglong2* Kp = (const ulonglong2*)sm.Ks + g * 2;
#pragma unroll 4
        for (int i = 0; i < 128; ++i) {          // keys g, g+4, g+8, ...
            ulonglong2 kA = Kp[i * 8 + 0];
            ulonglong2 kB = Kp[i * 8 + 1];
            unsigned long long d2 =
                fma2(q01, kA.x, fma2(q23, kA.y, fma2(q45, kB.x, mul2(q67, kB.y))));
            float dl, dh; upk2(d2, dl, dh);
            float w;
            asm("ex2.approx.f32 %0, %1;" : "=f"(w) : "f"(dl + dh));
            l += w;
            unsigned long long w2 = pk2(w, w);
            acc01 = fma2(w2, kA.x, acc01);
            acc23 = fma2(w2, kA.y, acc23);
            acc45 = fma2(w2, kB.x, acc45);
            acc67 = fma2(w2, kB.y, acc67);
        }

        float a[9];
        upk2(acc01, a[0], a[1]);
        upk2(acc23, a[2], a[3]);
        upk2(acc45, a[4], a[5]);
        upk2(acc67, a[6], a[7]);
        a[8] = l;
#pragma unroll
        for (int v = 0; v < 9; ++v) {
            a[v] += __shfl_xor_sync(0xffffffffu, a[v], 1);
            a[v] += __shfl_xor_sync(0xffffffffu, a[v], 2);
        }

        if (g == 0) {
            float inv = 1.f / a[8];
            float* cp = g_ctx + ((size_t)(b * S + q)) * E + h * 8;
            *(float4*)(cp + 0) = make_float4(a[0] * inv, a[1] * inv, a[2] * inv, a[3] * inv);
            *(float4*)(cp + 4) = make_float4(a[4] * inv, a[5] * inv, a[6] * inv, a[7] * inv);
        }
    }

    // ======================= Grid barrier ===================================
    __threadfence();                 // make this thread's ctx writes visible
    __syncthreads();
    if (tid == 0) {
        unsigned int old = g_bar_phase;
        unsigned int a = atomicAdd(&g_bar_count, 1u);
        if (a == NBLK - 1u) {
            g_bar_count = 0u;        // reset for next graph replay
            __threadfence();
            g_bar_phase = old + 1u;
        } else {
            while (g_bar_phase == old) { __nanosleep(32); }
        }
    }
    __syncthreads();
    __threadfence();

    // ======================= Phase 2: projection ============================
    // out[n, e] = sum_k ctx[n, k] * W[e, k] + b[e]
    for (int i = tid; i < 64 * 64; i += NTHR) {   // transpose W into smem
        int e = i >> 6, k = i & 63;
        sm.p2.Wt[k][e] = W[i];
    }
    if (tid < 64) sm.p2.bs[tid] = bo[tid];
    __syncthreads();

    const int warp = tid >> 5;        // 0..15 -> one row per warp
    const int lane = tid & 31;
    const int n  = bid * 16 + warp;   // 0..4095
    const int e0 = lane * 2;

    const float4* crow = (const float4*)(g_ctx + (size_t)n * 64);
    unsigned long long acc = pk2(sm.p2.bs[e0], sm.p2.bs[e0 + 1]);

#pragma unroll
    for (int k4 = 0; k4 < 16; ++k4) {
        float4 c = __ldg(crow + k4);  // warp-broadcast: 1 line
        const int k0 = k4 * 4;
        acc = fma2(pk2(c.x, c.x), *(const unsigned long long*)&sm.p2.Wt[k0 + 0][e0], acc);
        acc = fma2(pk2(c.y, c.y), *(const unsigned long long*)&sm.p2.Wt[k0 + 1][e0], acc);
        acc = fma2(pk2(c.z, c.z), *(const unsigned long long*)&sm.p2.Wt[k0 + 2][e0], acc);
        acc = fma2(pk2(c.w, c.w), *(const unsigned long long*)&sm.p2.Wt[k0 + 3][e0], acc);
    }

    float o0, o1; upk2(acc, o0, o1);
    *(float2*)(out + (size_t)n * 64 + e0) = make_float2(o0, o1);
}

extern "C" void kernel_launch(void* const* d_in, const int* in_sizes, int n_in,
                              void* d_out, int out_size)
{
    const float* x     = (const float*)d_in[0];  // [8, 512, 64]
    const float* theta = (const float*)d_in[1];  // [8]
    const float* W_o   = (const float*)d_in[2];  // [64, 64]
    const float* b_o   = (const float*)d_in[3];  // [64]
    float* out = (float*)d_out;

    fused_kernel<<<NBLK, NTHR>>>(x, theta, W_o, b_o, out);
}

// round 7
// speedup vs baseline: 1.1361x; 1.1361x over previous
#include <cuda_runtime.h>
#include <cuda_bf16.h>

#define B 8
#define S 512
#define E 64
#define H 8
#define BH (B*H)

__device__ float g_ctx[B * S * E];

// ---- packed f32x2 helpers (sm_103a) ---------------------------------------
__device__ __forceinline__ unsigned long long pk2(float lo, float hi) {
    unsigned long long r;
    asm("mov.b64 %0, {%1, %2};" : "=l"(r) : "f"(lo), "f"(hi));
    return r;
}
__device__ __forceinline__ void upk2(unsigned long long v, float& lo, float& hi) {
    asm("mov.b64 {%0, %1}, %2;" : "=f"(lo), "=f"(hi) : "l"(v));
}
__device__ __forceinline__ unsigned long long fma2(unsigned long long a,
                                                   unsigned long long b,
                                                   unsigned long long c) {
    unsigned long long d;
    asm("fma.rn.f32x2 %0, %1, %2, %3;" : "=l"(d) : "l"(a), "l"(b), "l"(c));
    return d;
}
__device__ __forceinline__ unsigned long long mul2(unsigned long long a,
                                                   unsigned long long b) {
    unsigned long long d;
    asm("mul.rn.f32x2 %0, %1, %2;" : "=l"(d) : "l"(a), "l"(b));
    return d;
}
__device__ __forceinline__ unsigned long long add2(unsigned long long a,
                                                   unsigned long long b) {
    unsigned long long d;
    asm("add.rn.f32x2 %0, %1, %2;" : "=l"(d) : "l"(a), "l"(b));
    return d;
}

// ---------------------------------------------------------------------------
// Kernel 1: quantum heads (analytic cos prefix products) + attention.
// Q=2 register blocking: 256 blocks x 256 threads; thread = (query pair, g).
// Queries q and q+64 share one key stream -> 2x ILP, half the LDS traffic.
// Key split g=0..3, keys 4i+g: conflict-free broadcast LDS (proven R2 pattern).
// ---------------------------------------------------------------------------
__global__ __launch_bounds__(256) void qattn_kernel(
    const float* __restrict__ x,      // [B, S, E]
    const float* __restrict__ theta,  // [8]
    float* __restrict__ ctx)          // [B*S, 64]
{
    __shared__ __align__(16) float Ks[S * 8];   // 16 KB

    const int bh  = blockIdx.y;
    const int b   = bh >> 3;
    const int h   = bh & 7;
    const int tid = threadIdx.x;      // 0..255

    float th[8];
#pragma unroll
    for (int j = 0; j < 8; ++j) th[j] = __ldg(theta + j);

    // Build K: 2 rows per thread.
#pragma unroll
    for (int rr = 0; rr < 2; ++rr) {
        const int s = tid + rr * 256;
        const float* xr = x + ((size_t)(b * S + s)) * E + h * 8;
        float4 v0 = *(const float4*)(xr);
        float4 v1 = *(const float4*)(xr + 4);
        float c0 = __cosf(v0.x + th[0]);
        float c1 = __cosf(v0.y + th[1]);
        float c2 = __cosf(v0.z + th[2]);
        float c3 = __cosf(v0.w + th[3]);
        float c4 = __cosf(v1.x + th[4]);
        float c5 = __cosf(v1.y + th[5]);
        float c6 = __cosf(v1.z + th[6]);
        float c7 = __cosf(v1.w + th[7]);
        float q1 = c0 * c1;
        float q2 = q1 * c2;
        float q3 = q2 * c3;
        float q4 = q3 * c4;
        float q5 = q4 * c5;
        float q6 = q5 * c6;
        float q7 = q6 * c7;
        float q0 = c1 * c2 * c3 * c4 * c5 * c6 * c7;
        ((float4*)Ks)[s * 2 + 0] = make_float4(q0, q1, q2, q3);
        ((float4*)Ks)[s * 2 + 1] = make_float4(q4, q5, q6, q7);
    }
    __syncthreads();

    const int qi = tid >> 2;                    // 0..63
    const int g  = tid & 3;                     // key-split lane
    const int q0 = blockIdx.x * 128 + qi;       // query rows q0 and q0+64
    const int q1 = q0 + 64;

    const float sc = 0.35355339059327373f * 1.4426950408889634f; // scale*log2e

    float4 a0 = ((const float4*)Ks)[q0 * 2 + 0];
    float4 a1 = ((const float4*)Ks)[q0 * 2 + 1];
    float4 b0 = ((const float4*)Ks)[q1 * 2 + 0];
    float4 b1 = ((const float4*)Ks)[q1 * 2 + 1];
    unsigned long long qA01 = pk2(a0.x * sc, a0.y * sc);
    unsigned long long qA23 = pk2(a0.z * sc, a0.w * sc);
    unsigned long long qA45 = pk2(a1.x * sc, a1.y * sc);
    unsigned long long qA67 = pk2(a1.z * sc, a1.w * sc);
    unsigned long long qB01 = pk2(b0.x * sc, b0.y * sc);
    unsigned long long qB23 = pk2(b0.z * sc, b0.w * sc);
    unsigned long long qB45 = pk2(b1.x * sc, b1.y * sc);
    unsigned long long qB67 = pk2(b1.z * sc, b1.w * sc);

    unsigned long long accA01 = 0ull, accA23 = 0ull, accA45 = 0ull, accA67 = 0ull;
    unsigned long long accB01 = 0ull, accB23 = 0ull, accB45 = 0ull, accB67 = 0ull;
    float lA = 0.f, lB = 0.f;

    const ulonglong2* Kp = (const ulonglong2*)Ks + g * 2;
#pragma unroll 4
    for (int i = 0; i < 128; ++i) {             // keys g, g+4, g+8, ...
        ulonglong2 kA = Kp[i * 8 + 0];          // (k0,k1),(k2,k3)
        ulonglong2 kB = Kp[i * 8 + 1];          // (k4,k5),(k6,k7)

        // tree-shaped dots: two independent depth-2 chains per query
        unsigned long long tA0 = fma2(qA23, kA.y, mul2(qA01, kA.x));
        unsigned long long tA1 = fma2(qA67, kB.y, mul2(qA45, kB.x));
        unsigned long long tB0 = fma2(qB23, kA.y, mul2(qB01, kA.x));
        unsigned long long tB1 = fma2(qB67, kB.y, mul2(qB45, kB.x));
        unsigned long long dA = add2(tA0, tA1);
        unsigned long long dB = add2(tB0, tB1);
        float dAl, dAh, dBl, dBh;
        upk2(dA, dAl, dAh);
        upk2(dB, dBl, dBh);
        float wa, wb;
        asm("ex2.approx.f32 %0, %1;" : "=f"(wa) : "f"(dAl + dAh));
        asm("ex2.approx.f32 %0, %1;" : "=f"(wb) : "f"(dBl + dBh));
        lA += wa;
        lB += wb;
        unsigned long long w2a = pk2(wa, wa);
        unsigned long long w2b = pk2(wb, wb);
        accA01 = fma2(w2a, kA.x, accA01);
        accA23 = fma2(w2a, kA.y, accA23);
        accA45 = fma2(w2a, kB.x, accA45);
        accA67 = fma2(w2a, kB.y, accA67);
        accB01 = fma2(w2b, kA.x, accB01);
        accB23 = fma2(w2b, kA.y, accB23);
        accB45 = fma2(w2b, kB.x, accB45);
        accB67 = fma2(w2b, kB.y, accB67);
    }

    // reduce across the 4 split lanes (consecutive lanes within warp)
    float r[18];
    upk2(accA01, r[0], r[1]);
    upk2(accA23, r[2], r[3]);
    upk2(accA45, r[4], r[5]);
    upk2(accA67, r[6], r[7]);
    r[8] = lA;
    upk2(accB01, r[9], r[10]);
    upk2(accB23, r[11], r[12]);
    upk2(accB45, r[13], r[14]);
    upk2(accB67, r[15], r[16]);
    r[17] = lB;
#pragma unroll
    for (int v = 0; v < 18; ++v) {
        r[v] += __shfl_xor_sync(0xffffffffu, r[v], 1);
        r[v] += __shfl_xor_sync(0xffffffffu, r[v], 2);
    }

    if (g == 0) {
        float invA = 1.f / r[8];
        float* cpA = g_ctx; // silence unused warning pattern
        float* cp0 = ctx + ((size_t)(b * S + q0)) * E + h * 8;
        *(float4*)(cp0 + 0) = make_float4(r[0] * invA, r[1] * invA, r[2] * invA, r[3] * invA);
        *(float4*)(cp0 + 4) = make_float4(r[4] * invA, r[5] * invA, r[6] * invA, r[7] * invA);
        float invB = 1.f / r[17];
        float* cp1 = ctx + ((size_t)(b * S + q1)) * E + h * 8;
        *(float4*)(cp1 + 0) = make_float4(r[9] * invB, r[10] * invB, r[11] * invB, r[12] * invB);
        *(float4*)(cp1 + 4) = make_float4(r[13] * invB, r[14] * invB, r[15] * invB, r[16] * invB);
        (void)cpA;
    }
}

// ---------------------------------------------------------------------------
// Kernel 2: out = ctx @ W^T + b. NO transpose: W kept row-major in smem with
// pad 65 -> per-lane-e scalar LDS has banks (e + k) % 32: conflict-free.
// 128 blocks x 256 threads, 32 rows/block. Warp: lane owns outputs e=lane and
// e=lane+32 for 4 rows; k-outer loop: 2 W-loads + 4 c-broadcasts + 8 FMA.
// ---------------------------------------------------------------------------
__global__ __launch_bounds__(256) void proj_kernel(
    const float* __restrict__ ctx,   // [4096, 64]
    const float* __restrict__ W,     // [64, 64]  (e, k)
    const float* __restrict__ bo,    // [64]
    float* __restrict__ out)         // [4096, 64]
{
    __shared__ float Ws[64 * 65];    // Ws[e*65 + k]
    __shared__ float Cs[32 * 65];    // Cs[r*65 + k]
    __shared__ float bs[64];

    const int tid  = threadIdx.x;     // 0..255
    const int row0 = blockIdx.x * 32;

    // Load W (coalesced float4 LDG, scalar STS ~2-way conflicts, one-time).
    for (int i = tid * 4; i < 64 * 64; i += 256 * 4) {
        float4 w = __ldg((const float4*)(W + i));
        int e = i >> 6, k = i & 63;
        float* p = &Ws[e * 65 + k];
        p[0] = w.x; p[1] = w.y; p[2] = w.z; p[3] = w.w;
    }
    // Load ctx tile.
    for (int i = tid * 4; i < 32 * 64; i += 256 * 4) {
        float4 c = __ldg((const float4*)(ctx + (size_t)row0 * 64 + i));
        int r = i >> 6, k = i & 63;
        float* p = &Cs[r * 65 + k];
        p[0] = c.x; p[1] = c.y; p[2] = c.z; p[3] = c.w;
    }
    if (tid < 64) bs[tid] = bo[tid];
    __syncthreads();

    const int warp = tid >> 5;        // 0..7 -> rows warp*4 .. warp*4+3
    const int lane = tid & 31;
    const int r0   = warp * 4;

    float acc[4][2];
#pragma unroll
    for (int j = 0; j < 4; ++j) { acc[j][0] = bs[lane]; acc[j][1] = bs[lane + 32]; }

#pragma unroll 8
    for (int k = 0; k < 64; ++k) {
        float w0 = Ws[lane * 65 + k];          // banks (lane+k)%32: conflict-free
        float w1 = Ws[(lane + 32) * 65 + k];
#pragma unroll
        for (int j = 0; j < 4; ++j) {
            float c = Cs[(r0 + j) * 65 + k];   // broadcast
            acc[j][0] = fmaf(c, w0, acc[j][0]);
            acc[j][1] = fmaf(c, w1, acc[j][1]);
        }
    }

#pragma unroll
    for (int j = 0; j < 4; ++j) {
        float* orow = out + (size_t)(row0 + r0 + j) * 64;
        orow[lane]      = acc[j][0];
        orow[lane + 32] = acc[j][1];
    }
}

extern "C" void kernel_launch(void* const* d_in, const int* in_sizes, int n_in,
                              void* d_out, int out_size)
{
    const float* x     = (const float*)d_in[0];  // [8, 512, 64]
    const float* theta = (const float*)d_in[1];  // [8]
    const float* W_o   = (const float*)d_in[2];  // [64, 64]
    const float* b_o   = (const float*)d_in[3];  // [64]
    float* out = (float*)d_out;

    float* ctx;
    cudaGetSymbolAddress((void**)&ctx, g_ctx);

    dim3 grid1(S / 128, BH);             // (4, 64) = 256 blocks x 256 thr
    qattn_kernel<<<grid1, 256>>>(x, theta, ctx);

    proj_kernel<<<(B * S) / 32, 256>>>(ctx, W_o, b_o, out);
}

// round 8
// speedup vs baseline: 1.1411x; 1.0044x over previous
#include <cuda_runtime.h>
#include <cuda_bf16.h>

#define B 8
#define S 512
#define E 64
#define H 8
#define BH (B*H)
#define RSTRIDE 12   // floats per key row (48B): g*12%32 distinct quads for g=0..7

__device__ float g_ctx[B * S * E];

// ---- packed f32x2 helpers (sm_103a) ---------------------------------------
__device__ __forceinline__ unsigned long long pk2(float lo, float hi) {
    unsigned long long r;
    asm("mov.b64 %0, {%1, %2};" : "=l"(r) : "f"(lo), "f"(hi));
    return r;
}
__device__ __forceinline__ void upk2(unsigned long long v, float& lo, float& hi) {
    asm("mov.b64 {%0, %1}, %2;" : "=f"(lo), "=f"(hi) : "l"(v));
}
__device__ __forceinline__ unsigned long long fma2(unsigned long long a,
                                                   unsigned long long b,
                                                   unsigned long long c) {
    unsigned long long d;
    asm("fma.rn.f32x2 %0, %1, %2, %3;" : "=l"(d) : "l"(a), "l"(b), "l"(c));
    return d;
}
__device__ __forceinline__ unsigned long long mul2(unsigned long long a,
                                                   unsigned long long b) {
    unsigned long long d;
    asm("mul.rn.f32x2 %0, %1, %2;" : "=l"(d) : "l"(a), "l"(b));
    return d;
}
__device__ __forceinline__ unsigned long long add2(unsigned long long a,
                                                   unsigned long long b) {
    unsigned long long d;
    asm("add.rn.f32x2 %0, %1, %2;" : "=l"(d) : "l"(a), "l"(b));
    return d;
}

// ---------------------------------------------------------------------------
// Kernel 1: quantum heads (analytic cos prefix products) + attention.
// grid (8, 64) = 512 blocks x 256 threads = 4096 warps (27.7/SM).
// Thread = (query pair, g): queries q0,q0+32 share one key stream (Q=2 ILP).
// Key split g=0..7, keys 8i+g; 48B row stride makes the 8 g-lanes hit 8
// distinct bank quads -> conflict-free broadcast LDS.128.
// ---------------------------------------------------------------------------
__global__ __launch_bounds__(256) void qattn_kernel(
    const float* __restrict__ x,      // [B, S, E]
    const float* __restrict__ theta,  // [8]
    float* __restrict__ ctx)          // [B*S, 64]
{
    __shared__ __align__(16) float Ks[S * RSTRIDE];   // 24 KB

    const int bh  = blockIdx.y;
    const int b   = bh >> 3;
    const int h   = bh & 7;
    const int tid = threadIdx.x;      // 0..255

    float th[8];
#pragma unroll
    for (int j = 0; j < 8; ++j) th[j] = __ldg(theta + j);

    // Build K: 2 rows per thread (48B stride, 16B-aligned halves).
#pragma unroll
    for (int rr = 0; rr < 2; ++rr) {
        const int s = tid + rr * 256;
        const float* xr = x + ((size_t)(b * S + s)) * E + h * 8;
        float4 v0 = *(const float4*)(xr);
        float4 v1 = *(const float4*)(xr + 4);
        float c0 = __cosf(v0.x + th[0]);
        float c1 = __cosf(v0.y + th[1]);
        float c2 = __cosf(v0.z + th[2]);
        float c3 = __cosf(v0.w + th[3]);
        float c4 = __cosf(v1.x + th[4]);
        float c5 = __cosf(v1.y + th[5]);
        float c6 = __cosf(v1.z + th[6]);
        float c7 = __cosf(v1.w + th[7]);
        float q1 = c0 * c1;
        float q2 = q1 * c2;
        float q3 = q2 * c3;
        float q4 = q3 * c4;
        float q5 = q4 * c5;
        float q6 = q5 * c6;
        float q7 = q6 * c7;
        float q0 = c1 * c2 * c3 * c4 * c5 * c6 * c7;
        *(float4*)&Ks[s * RSTRIDE]     = make_float4(q0, q1, q2, q3);
        *(float4*)&Ks[s * RSTRIDE + 4] = make_float4(q4, q5, q6, q7);
    }
    __syncthreads();

    const int qi = tid >> 3;                    // 0..31
    const int g  = tid & 7;                     // key-split lane (8-way)
    const int q0 = blockIdx.x * 64 + qi;        // query rows q0, q0+32
    const int q1 = q0 + 32;

    const float sc = 0.35355339059327373f * 1.4426950408889634f; // scale*log2e

    float4 a0 = *(const float4*)&Ks[q0 * RSTRIDE];
    float4 a1 = *(const float4*)&Ks[q0 * RSTRIDE + 4];
    float4 b0 = *(const float4*)&Ks[q1 * RSTRIDE];
    float4 b1 = *(const float4*)&Ks[q1 * RSTRIDE + 4];
    unsigned long long qA01 = pk2(a0.x * sc, a0.y * sc);
    unsigned long long qA23 = pk2(a0.z * sc, a0.w * sc);
    unsigned long long qA45 = pk2(a1.x * sc, a1.y * sc);
    unsigned long long qA67 = pk2(a1.z * sc, a1.w * sc);
    unsigned long long qB01 = pk2(b0.x * sc, b0.y * sc);
    unsigned long long qB23 = pk2(b0.z * sc, b0.w * sc);
    unsigned long long qB45 = pk2(b1.x * sc, b1.y * sc);
    unsigned long long qB67 = pk2(b1.z * sc, b1.w * sc);

    unsigned long long accA01 = 0ull, accA23 = 0ull, accA45 = 0ull, accA67 = 0ull;
    unsigned long long accB01 = 0ull, accB23 = 0ull, accB45 = 0ull, accB67 = 0ull;
    float lA = 0.f, lB = 0.f;

    const float* kp = Ks + g * RSTRIDE;         // row g; rows advance by 8
#pragma unroll 4
    for (int i = 0; i < 64; ++i) {              // keys g, g+8, g+16, ...
        ulonglong2 kA = *(const ulonglong2*)(kp + i * (8 * RSTRIDE));
        ulonglong2 kB = *(const ulonglong2*)(kp + i * (8 * RSTRIDE) + 4);

        unsigned long long tA0 = fma2(qA23, kA.y, mul2(qA01, kA.x));
        unsigned long long tA1 = fma2(qA67, kB.y, mul2(qA45, kB.x));
        unsigned long long tB0 = fma2(qB23, kA.y, mul2(qB01, kA.x));
        unsigned long long tB1 = fma2(qB67, kB.y, mul2(qB45, kB.x));
        unsigned long long dA = add2(tA0, tA1);
        unsigned long long dB = add2(tB0, tB1);
        float dAl, dAh, dBl, dBh;
        upk2(dA, dAl, dAh);
        upk2(dB, dBl, dBh);
        float wa, wb;
        asm("ex2.approx.f32 %0, %1;" : "=f"(wa) : "f"(dAl + dAh));
        asm("ex2.approx.f32 %0, %1;" : "=f"(wb) : "f"(dBl + dBh));
        lA += wa;
        lB += wb;
        unsigned long long w2a = pk2(wa, wa);
        unsigned long long w2b = pk2(wb, wb);
        accA01 = fma2(w2a, kA.x, accA01);
        accA23 = fma2(w2a, kA.y, accA23);
        accA45 = fma2(w2a, kB.x, accA45);
        accA67 = fma2(w2a, kB.y, accA67);
        accB01 = fma2(w2b, kA.x, accB01);
        accB23 = fma2(w2b, kA.y, accB23);
        accB45 = fma2(w2b, kB.x, accB45);
        accB67 = fma2(w2b, kB.y, accB67);
    }

    // reduce across the 8 split lanes (contiguous within the warp)
    float r[18];
    upk2(accA01, r[0], r[1]);
    upk2(accA23, r[2], r[3]);
    upk2(accA45, r[4], r[5]);
    upk2(accA67, r[6], r[7]);
    r[8] = lA;
    upk2(accB01, r[9], r[10]);
    upk2(accB23, r[11], r[12]);
    upk2(accB45, r[13], r[14]);
    upk2(accB67, r[15], r[16]);
    r[17] = lB;
#pragma unroll
    for (int v = 0; v < 18; ++v) {
        r[v] += __shfl_xor_sync(0xffffffffu, r[v], 1);
        r[v] += __shfl_xor_sync(0xffffffffu, r[v], 2);
        r[v] += __shfl_xor_sync(0xffffffffu, r[v], 4);
    }

    if (g == 0) {
        float invA = 1.f / r[8];
        float* cp0 = ctx + ((size_t)(b * S + q0)) * E + h * 8;
        *(float4*)(cp0 + 0) = make_float4(r[0] * invA, r[1] * invA, r[2] * invA, r[3] * invA);
        *(float4*)(cp0 + 4) = make_float4(r[4] * invA, r[5] * invA, r[6] * invA, r[7] * invA);
        float invB = 1.f / r[17];
        float* cp1 = ctx + ((size_t)(b * S + q1)) * E + h * 8;
        *(float4*)(cp1 + 0) = make_float4(r[9] * invB, r[10] * invB, r[11] * invB, r[12] * invB);
        *(float4*)(cp1 + 4) = make_float4(r[13] * invB, r[14] * invB, r[15] * invB, r[16] * invB);
    }
}

// ---------------------------------------------------------------------------
// Kernel 2: out = ctx @ W^T + b. Pad-65 row-major W in smem: per-lane-e scalar
// LDS has banks (e + k) % 32 -> conflict-free, no transpose.
// 256 blocks x 128 threads, 16 rows/block (1.73 blocks/SM overlaps prologue).
// ---------------------------------------------------------------------------
__global__ __launch_bounds__(128) void proj_kernel(
    const float* __restrict__ ctx,   // [4096, 64]
    const float* __restrict__ W,     // [64, 64]  (e, k)
    const float* __restrict__ bo,    // [64]
    float* __restrict__ out)         // [4096, 64]
{
    __shared__ float Ws[64 * 65];    // Ws[e*65 + k]
    __shared__ float Cs[16 * 65];    // Cs[r*65 + k]
    __shared__ float bs[64];

    const int tid  = threadIdx.x;     // 0..127
    const int row0 = blockIdx.x * 16;

    for (int i = tid * 4; i < 64 * 64; i += 128 * 4) {
        float4 w = __ldg((const float4*)(W + i));
        int e = i >> 6, k = i & 63;
        float* p = &Ws[e * 65 + k];
        p[0] = w.x; p[1] = w.y; p[2] = w.z; p[3] = w.w;
    }
    for (int i = tid * 4; i < 16 * 64; i += 128 * 4) {
        float4 c = __ldg((const float4*)(ctx + (size_t)row0 * 64 + i));
        int r = i >> 6, k = i & 63;
        float* p = &Cs[r * 65 + k];
        p[0] = c.x; p[1] = c.y; p[2] = c.z; p[3] = c.w;
    }
    if (tid < 64) bs[tid] = bo[tid];
    __syncthreads();

    const int warp = tid >> 5;        // 0..3 -> rows warp*4 .. warp*4+3
    const int lane = tid & 31;
    const int r0   = warp * 4;

    float acc[4][2];
#pragma unroll
    for (int j = 0; j < 4; ++j) { acc[j][0] = bs[lane]; acc[j][1] = bs[lane + 32]; }

#pragma unroll 8
    for (int k = 0; k < 64; ++k) {
        float w0 = Ws[lane * 65 + k];          // banks (lane+k)%32: conflict-free
        float w1 = Ws[(lane + 32) * 65 + k];
#pragma unroll
        for (int j = 0; j < 4; ++j) {
            float c = Cs[(r0 + j) * 65 + k];   // broadcast
            acc[j][0] = fmaf(c, w0, acc[j][0]);
            acc[j][1] = fmaf(c, w1, acc[j][1]);
        }
    }

#pragma unroll
    for (int j = 0; j < 4; ++j) {
        float* orow = out + (size_t)(row0 + r0 + j) * 64;
        orow[lane]      = acc[j][0];
        orow[lane + 32] = acc[j][1];
    }
}

extern "C" void kernel_launch(void* const* d_in, const int* in_sizes, int n_in,
                              void* d_out, int out_size)
{
    const float* x     = (const float*)d_in[0];  // [8, 512, 64]
    const float* theta = (const float*)d_in[1];  // [8]
    const float* W_o   = (const float*)d_in[2];  // [64, 64]
    const float* b_o   = (const float*)d_in[3];  // [64]
    float* out = (float*)d_out;

    float* ctx;
    cudaGetSymbolAddress((void**)&ctx, g_ctx);

    dim3 grid1(S / 64, BH);              // (8, 64) = 512 blocks x 256 thr
    qattn_kernel<<<grid1, 256>>>(x, theta, ctx);

    proj_kernel<<<(B * S) / 16, 128>>>(ctx, W_o, b_o, out);
}